// round 16
// baseline (speedup 1.0000x reference)
#include <cuda_runtime.h>
#include <cstdint>

#define B_    256
#define DIN   700
#define T_    250
#define H_    1024
#define DOUT  20
#define NW    8        // 32-bit words covering T_=250 bits
#define DINP  704      // padded DIN
#define MAXL  256      // max active inputs per (b,t) list (multiple of 8)
#define NROW  (B_*T_)  // 64000
#define NPAIR (NROW/2) // 32000
#define HS    64       // h columns per phase-A slice
#define NSLICE (H_/HS) // 16
#define NGRP  37       // interleave groups
#define NSS   4        // super-slices (4 slices each)
#define GRID_A (NGRP*NSS)                            // 148
#define PPG37 ((NPAIR + NGRP - 1) / NGRP)            // 865
#define ZROW  DIN      // dummy zero W row index (row 700)
#define ZPACK 0x02BC02BCu                            // two packed ZROW u16s
#define NBIN  33
#define WPAD  22       // padded sWT/sO row stride in floats (88 B: gcd(11,16)=1)

#define PACK_BLK ((B_*DIN + 7) / 8)                 // 22400
#define WT_BLK   704                                 // 22 i-tiles x 32 h-tiles
#define WO_BLK   80                                  // H_*DOUT / 256
#define LIST_BLK (B_*NW)                             // 2048

// ---------------- scratch (static device memory; no allocations) -------------
__device__ float          g_Wt[(DIN+1)*H_];                 // W_hid^T [i][h], row 700 = zeros
__device__ float          g_WoT[H_*DOUT];                   // W_out^T  [h][o]
__device__ unsigned       g_words[B_*NW*DINP];              // spike bits
__device__ unsigned short g_lists[(size_t)NROW*MAXL];       // active input indices per (b,t)
__device__ int            g_counts[NROW];                   // padded counts (multiple of 8)
__device__ int            g_order[NROW];                    // rows grouped by count bin
__device__ int            g_binhist[NBIN];                  // bin histogram
__device__ int            g_bincur[NBIN];                   // scatter cursors (prefix bases)
__device__ int            g_done;                           // k_lists completion counter
__device__ float          g_I[(size_t)NROW*H_];             // hidden input currents [b][t][h]
__device__ unsigned       g_hsb[(size_t)NROW*(H_/32)];      // hidden spike bits [b][t][h/32]

// ---------------- K0: fused pack + tiled transposes + counter init -------------
__global__ void k_prep(const float* __restrict__ sd, const float* __restrict__ Wh,
                       const float* __restrict__ Wo) {
    if (blockIdx.x < PACK_BLK) {
        int gw   = blockIdx.x * 8 + (threadIdx.x >> 5);
        int lane = threadIdx.x & 31;
        if (gw >= B_ * DIN) return;
        int b = gw / DIN, i = gw % DIN;
        const float* p = sd + ((size_t)b * DIN + i) * T_;
#pragma unroll
        for (int w = 0; w < NW; w++) {
            int t = w * 32 + lane;
            float v = (t < T_) ? p[t] : 0.0f;
            unsigned m = __ballot_sync(0xffffffffu, v > 0.5f);
            if (lane == 0) g_words[(b * NW + w) * DINP + i] = m;
        }
    } else if (blockIdx.x < PACK_BLK + WT_BLK) {
        __shared__ float tile[32][33];
        int bi = blockIdx.x - PACK_BLK;
        int it = bi >> 5;                         // 0..21
        int ht = bi & 31;                         // 0..31
        int i0 = it * 32, h0 = ht * 32;
        int tx = threadIdx.x & 31, ty = threadIdx.x >> 5;
#pragma unroll
        for (int k = 0; k < 4; k++) {             // coalesced Wh reads
            int h = h0 + ty + k * 8;
            int i = i0 + tx;
            tile[ty + k * 8][tx] = (i < DIN) ? Wh[h * DIN + i] : 0.0f;
        }
        __syncthreads();
#pragma unroll
        for (int k = 0; k < 4; k++) {             // coalesced Wt writes
            int i = i0 + ty + k * 8;
            int h = h0 + tx;
            if (i < DIN + 1) g_Wt[i * H_ + h] = tile[tx][ty + k * 8];
        }
    } else if (blockIdx.x < PACK_BLK + WT_BLK + WO_BLK) {
        int e = (blockIdx.x - PACK_BLK - WT_BLK) * 256 + threadIdx.x;  // < H_*DOUT
        int h = e / DOUT, o = e % DOUT;
        g_WoT[e] = Wo[o * H_ + h];
    } else {
        if (threadIdx.x < NBIN) {                 // re-zero every launch (graph replay)
            g_binhist[threadIdx.x] = 0;
            g_bincur[threadIdx.x] = 0;
        }
        if (threadIdx.x == NBIN) g_done = 0;
    }
}

// ---------------- K2a: index lists + histogram + last-block prefix ------------
__global__ void k_lists() {
    __shared__ unsigned sw[DINP];
    __shared__ int lh[NBIN];
    __shared__ bool last;
    int b = blockIdx.x / NW, w = blockIdx.x % NW;
    if (threadIdx.x < NBIN) lh[threadIdx.x] = 0;
    for (int i = threadIdx.x; i < DIN; i += blockDim.x)
        sw[i] = g_words[(b * NW + w) * DINP + i];
    __syncthreads();
    int wi = threadIdx.x >> 5, lane = threadIdx.x & 31;
    for (int tt = wi; tt < 32; tt += 8) {
        int t = w * 32 + tt;
        if (t >= T_) continue;
        int row = b * T_ + t;
        unsigned short* lst = &g_lists[(size_t)row * MAXL];
        int cnt = 0;
        for (int base = 0; base < DINP; base += 32) {
            int i = base + lane;
            unsigned hit = (i < DIN) ? ((sw[i] >> tt) & 1u) : 0u;
            unsigned m = __ballot_sync(0xffffffffu, hit != 0u);
            if (hit) {
                int pos = cnt + __popc(m & ((1u << lane) - 1u));
                if (pos < MAXL) lst[pos] = (unsigned short)i;
            }
            cnt += __popc(m);
        }
        cnt = min(cnt, MAXL);
        int cnt_pad = (cnt + 7) & ~7;
        if (cnt + lane < cnt_pad) lst[cnt + lane] = (unsigned short)ZROW;
        if (lane == 0) {
            g_counts[row] = cnt_pad;
            atomicAdd(&lh[cnt_pad >> 3], 1);
        }
    }
    __syncthreads();
    if (threadIdx.x < NBIN && lh[threadIdx.x])
        atomicAdd(&g_binhist[threadIdx.x], lh[threadIdx.x]);
    // last block computes the exclusive prefix into g_bincur
    __threadfence();
    __syncthreads();
    if (threadIdx.x == 0)
        last = (atomicAdd(&g_done, 1) == LIST_BLK - 1);
    __syncthreads();
    if (last && threadIdx.x == 0) {
        int s = 0;
#pragma unroll
        for (int bin = 0; bin < NBIN; bin++) { int v = g_binhist[bin]; g_bincur[bin] = s; s += v; }
    }
}

// ---------------- K2q: warp-aggregated scatter of rows into bins ----------------
__global__ void k_place() {
    int row = blockIdx.x * 256 + threadIdx.x;
    int lane = threadIdx.x & 31;
    int bin = g_counts[row] >> 3;
    unsigned peers = __match_any_sync(0xffffffffu, bin);
    int leader = __ffs(peers) - 1;
    int rank = __popc(peers & ((1u << lane) - 1u));
    int base = 0;
    if (lane == leader) base = atomicAdd(&g_bincur[bin], __popc(peers));
    base = __shfl_sync(0xffffffffu, base, leader);
    g_order[base + rank] = row;
}

// ---------------- K2b: sparse hidden GEMM (I = xs @ W_hid^T) -------------------
// 148 blocks = 37 interleave groups x 4 super-slices. Each block walks its 4
// slices; within a slice, pairs q = bg + k*37 (uniform cost sampling of the
// sorted order). Warp = row pair; half-warp per row; f32x2 adds.
__global__ __launch_bounds__(1024, 1) void k_phaseA() {
    extern __shared__ float sW[];                // [(DIN+1)][HS]
    int warpId = threadIdx.x >> 5, lane = threadIdx.x & 31;
    int half = lane >> 4, hl = lane & 15;
    const char* sWb = (const char*)sW + hl * 16;

    int ss = blockIdx.x / NGRP;                   // 0..3 super-slice
    int bg = blockIdx.x % NGRP;                   // 0..36 interleave group

#pragma unroll 1
    for (int sli = 0; sli < 4; sli++) {
        int sl = ss * 4 + sli;
        int h0 = sl * HS;

        __syncthreads();                          // protect sW from previous slice
        for (int e = threadIdx.x; e < (DIN + 1) * (HS / 4); e += 1024) {
            int i = e >> 4, c = e & 15;
            ((float4*)sW)[e] = *(const float4*)&g_Wt[i * H_ + h0 + c * 4];
        }
        __syncthreads();

        for (int k = warpId; k < PPG37; k += 32) {
            int q = bg + k * NGRP;                // global pair id
            if (q >= NPAIR) break;
            int myrow = g_order[q * 2 + half];
            int mycnt = g_counts[myrow];
            int pcnt  = max(mycnt, __shfl_xor_sync(0xffffffffu, mycnt, 16));
            const unsigned short* lst = &g_lists[(size_t)myrow * MAXL];
            unsigned long long a0 = 0ull, a1 = 0ull;
            for (int base = 0; base < pcnt; base += 8) {
                uint4 cur;
                if (base < mycnt) cur = *(const uint4*)(lst + base);
                else              cur = make_uint4(ZPACK, ZPACK, ZPACK, ZPACK);
                unsigned j; ulonglong2 wv;
#define STEP(JE) \
                j = (JE); \
                wv = *(const ulonglong2*)(sWb + j * 256u); \
                asm("add.rn.f32x2 %0, %0, %1;" : "+l"(a0) : "l"(wv.x)); \
                asm("add.rn.f32x2 %0, %0, %1;" : "+l"(a1) : "l"(wv.y));
                STEP(cur.x & 0xFFFFu) STEP(cur.x >> 16)
                STEP(cur.y & 0xFFFFu) STEP(cur.y >> 16)
                STEP(cur.z & 0xFFFFu) STEP(cur.z >> 16)
                STEP(cur.w & 0xFFFFu) STEP(cur.w >> 16)
#undef STEP
            }
            ulonglong2 o; o.x = a0; o.y = a1;
            *(ulonglong2*)&g_I[(size_t)myrow * H_ + h0 + hl * 4] = o;
        }
    }
}

// ---------------- K3: hidden LIF recurrence + spike-bit pack -------------------
__global__ void k_rec_hid(const float* __restrict__ hs0, const float* __restrict__ hv0) {
    int b  = blockIdx.x >> 2;
    int hq = blockIdx.x & 3;
    int h  = hq * 256 + threadIdx.x;
    int lane = threadIdx.x & 31;
    float hv = hv0[b * H_ + h];
    float hs = hs0[b * H_ + h];
    const float* Ip = &g_I[(size_t)(b * T_) * H_ + h];
    unsigned* hp = &g_hsb[(size_t)(b * T_) * (H_ / 32) + (h >> 5)];

    for (int t = 0; t < T_; t += 10) {           // 250 % 10 == 0; deeper MLP
        float v[10];
#pragma unroll
        for (int k = 0; k < 10; k++) v[k] = Ip[(size_t)(t + k) * H_];
#pragma unroll
        for (int k = 0; k < 10; k++) {
            hv = hv * 0.5f * (1.0f - hs) + v[k];
            bool s = hv > 0.5f;
            hs = s ? 1.0f : 0.0f;
            unsigned m = __ballot_sync(0xffffffffu, s);
            if (lane == 0) hp[(size_t)(t + k) * (H_ / 32)] = m;
        }
    }
}

// ---------------- K4: out GEMM (sparse ffs walk) + fused out recurrence --------
// sWT/sO rows padded to WPAD=22 floats (88 B): divergent row reads sweep all
// 16 8B-banks (gcd(11,16)=1) -> near-conflict-free.
__global__ __launch_bounds__(256) void k_outgemm(const float* __restrict__ os0,
                                                 const float* __restrict__ ov0,
                                                 float* __restrict__ out) {
    extern __shared__ float smem_[];             // sWT [H_*22] + sO [256*22]
    float* sWT = smem_;
    float* sO  = smem_ + H_ * WPAD;
    {
        float2* d2 = (float2*)sWT;
        const float2* s2 = (const float2*)g_WoT;
        for (int e = threadIdx.x; e < H_ * (DOUT / 2); e += blockDim.x) {
            int h = e / (DOUT / 2), o2 = e % (DOUT / 2);
            d2[h * (WPAD / 2) + o2] = s2[e];
        }
    }
    __syncthreads();

    int b = blockIdx.x, t = threadIdx.x;
    if (t < T_) {
        const unsigned* wp_ = &g_hsb[(size_t)(b * T_ + t) * (H_ / 32)];
        float2 acc[10];
#pragma unroll
        for (int o = 0; o < 10; o++) acc[o] = make_float2(0.0f, 0.0f);
#pragma unroll 4
        for (int w = 0; w < H_ / 32; w++) {
            unsigned word = wp_[w];
            while (word) {
                int bit = __ffs(word) - 1;
                word &= word - 1;
                const float2* base = (const float2*)&sWT[(w * 32 + bit) * WPAD];
#pragma unroll
                for (int o = 0; o < 10; o++) {
                    float2 v = base[o];
                    acc[o].x += v.x; acc[o].y += v.y;
                }
            }
        }
        float2* od = (float2*)&sO[t * WPAD];
#pragma unroll
        for (int o = 0; o < 10; o++) od[o] = acc[o];
    }
    __syncthreads();

    if (t < DOUT) {
        float ov = ov0[b * DOUT + t];
        float os = os0[b * DOUT + t];
        float cnt = 0.0f;
        for (int tt = 0; tt < T_; tt++) {
            float v = sO[tt * WPAD + t];
            ov = ov * 0.5f * (1.0f - os) + v;
            os = (ov > 0.5f) ? 1.0f : 0.0f;
            cnt += os;
        }
        out[b * DOUT + t] = cnt;
    }
}

// ---------------- launch ------------------------------------------------------
extern "C" void kernel_launch(void* const* d_in, const int* in_sizes, int n_in,
                              void* d_out, int out_size) {
    const float* sd  = (const float*)d_in[0];   // spike_data [256,700,250]
    const float* Wh  = (const float*)d_in[1];   // W_hid [1024,700]
    const float* Wo  = (const float*)d_in[2];   // W_out [20,1024]
    const float* hs0 = (const float*)d_in[3];   // hid_spike0 [256,1024]
    const float* hv0 = (const float*)d_in[4];   // hid_volt0
    const float* os0 = (const float*)d_in[5];   // out_spike0 [256,20]
    const float* ov0 = (const float*)d_in[6];   // out_volt0
    float* out = (float*)d_out;                 // [256,20] fp32
    (void)in_sizes; (void)n_in; (void)out_size;

    int outg_smem = (H_ * WPAD + 256 * WPAD) * 4;   // 90 KB + 22.5 KB = 112.6 KB
    cudaFuncSetAttribute(k_phaseA, cudaFuncAttributeMaxDynamicSharedMemorySize, (DIN + 1) * HS * 4);
    cudaFuncSetAttribute(k_outgemm, cudaFuncAttributeMaxDynamicSharedMemorySize, outg_smem);

    k_prep   <<<PACK_BLK + WT_BLK + WO_BLK + 1, 256>>>(sd, Wh, Wo);
    k_lists  <<<LIST_BLK, 256>>>();
    k_place  <<<NROW / 256, 256>>>();
    k_phaseA <<<GRID_A, 1024, (DIN + 1) * HS * 4>>>();
    k_rec_hid<<<B_ * 4, 256>>>(hs0, hv0);
    k_outgemm<<<B_, 256, outg_smem>>>(os0, ov0, out);
}

// round 17
// speedup vs baseline: 1.0056x; 1.0056x over previous
#include <cuda_runtime.h>
#include <cstdint>

#define B_    256
#define DIN   700
#define T_    250
#define H_    1024
#define DOUT  20
#define NW    8        // 32-bit words covering T_=250 bits
#define DINP  704      // padded DIN
#define MAXL  256      // max active inputs per (b,t) list (multiple of 8)
#define NROW  (B_*T_)  // 64000
#define NPAIR (NROW/2) // 32000
#define HS    64       // h columns per phase-A slice
#define NGRP  37       // interleave groups
#define GRID_A 148                                   // 37 groups x 4 super-slices
#define PPG37 ((NPAIR + NGRP - 1) / NGRP)            // 865
#define RPB   ((NROW + GRID_A - 1) / GRID_A)         // 433 rows placed per block
#define ZROW  DIN      // dummy zero W row index (row 700)
#define ZPACK 0x02BC02BCu                            // two packed ZROW u16s
#define NBIN  33

#define PACK_BLK ((B_*DIN + 7) / 8)                 // 22400
#define WT_BLK   704                                 // 22 i-tiles x 32 h-tiles
#define WO_BLK   80                                  // H_*DOUT / 256
#define LIST_BLK (B_*NW)                             // 2048

// ---------------- scratch (static device memory; no allocations) -------------
__device__ float          g_Wt[(DIN+1)*H_];                 // W_hid^T [i][h], row 700 = zeros
__device__ float          g_WoT[H_*DOUT];                   // W_out^T  [h][o]
__device__ unsigned       g_words[B_*NW*DINP];              // spike bits
__device__ unsigned short g_lists[(size_t)NROW*MAXL];       // active input indices per (b,t)
__device__ int            g_counts[NROW];                   // padded counts (multiple of 8)
__device__ int            g_order[NROW];                    // rows grouped by count bin
__device__ int            g_binhist[NBIN];                  // bin histogram
__device__ int            g_bincur[NBIN];                   // scatter cursors (prefix bases)
__device__ int            g_done;                           // k_lists completion counter
__device__ volatile int   g_bar;                            // phaseA grid barrier
__device__ float          g_I[(size_t)NROW*H_];             // hidden input currents [b][t][h]
__device__ unsigned       g_hsb[(size_t)NROW*(H_/32)];      // hidden spike bits [b][t][h/32]

// ---------------- K0: fused pack + tiled transposes + counter init -------------
__global__ void k_prep(const float* __restrict__ sd, const float* __restrict__ Wh,
                       const float* __restrict__ Wo) {
    if (blockIdx.x < PACK_BLK) {
        int gw   = blockIdx.x * 8 + (threadIdx.x >> 5);
        int lane = threadIdx.x & 31;
        if (gw >= B_ * DIN) return;
        int b = gw / DIN, i = gw % DIN;
        const float* p = sd + ((size_t)b * DIN + i) * T_;
#pragma unroll
        for (int w = 0; w < NW; w++) {
            int t = w * 32 + lane;
            float v = (t < T_) ? p[t] : 0.0f;
            unsigned m = __ballot_sync(0xffffffffu, v > 0.5f);
            if (lane == 0) g_words[(b * NW + w) * DINP + i] = m;
        }
    } else if (blockIdx.x < PACK_BLK + WT_BLK) {
        __shared__ float tile[32][33];
        int bi = blockIdx.x - PACK_BLK;
        int it = bi >> 5;                         // 0..21
        int ht = bi & 31;                         // 0..31
        int i0 = it * 32, h0 = ht * 32;
        int tx = threadIdx.x & 31, ty = threadIdx.x >> 5;
#pragma unroll
        for (int k = 0; k < 4; k++) {             // coalesced Wh reads
            int h = h0 + ty + k * 8;
            int i = i0 + tx;
            tile[ty + k * 8][tx] = (i < DIN) ? Wh[h * DIN + i] : 0.0f;
        }
        __syncthreads();
#pragma unroll
        for (int k = 0; k < 4; k++) {             // coalesced Wt writes
            int i = i0 + ty + k * 8;
            int h = h0 + tx;
            if (i < DIN + 1) g_Wt[i * H_ + h] = tile[tx][ty + k * 8];
        }
    } else if (blockIdx.x < PACK_BLK + WT_BLK + WO_BLK) {
        int e = (blockIdx.x - PACK_BLK - WT_BLK) * 256 + threadIdx.x;  // < H_*DOUT
        int h = e / DOUT, o = e % DOUT;
        g_WoT[e] = Wo[o * H_ + h];
    } else {
        if (threadIdx.x < NBIN) {                 // re-zero every launch (graph replay)
            g_binhist[threadIdx.x] = 0;
            g_bincur[threadIdx.x] = 0;
        }
        if (threadIdx.x == NBIN) g_done = 0;
        if (threadIdx.x == NBIN + 1) g_bar = 0;
    }
}

// ---------------- K2a: index lists + histogram + last-block prefix ------------
__global__ void k_lists() {
    __shared__ unsigned sw[DINP];
    __shared__ int lh[NBIN];
    __shared__ bool last;
    int b = blockIdx.x / NW, w = blockIdx.x % NW;
    if (threadIdx.x < NBIN) lh[threadIdx.x] = 0;
    for (int i = threadIdx.x; i < DIN; i += blockDim.x)
        sw[i] = g_words[(b * NW + w) * DINP + i];
    __syncthreads();
    int wi = threadIdx.x >> 5, lane = threadIdx.x & 31;
    for (int tt = wi; tt < 32; tt += 8) {
        int t = w * 32 + tt;
        if (t >= T_) continue;
        int row = b * T_ + t;
        unsigned short* lst = &g_lists[(size_t)row * MAXL];
        int cnt = 0;
        for (int base = 0; base < DINP; base += 32) {
            int i = base + lane;
            unsigned hit = (i < DIN) ? ((sw[i] >> tt) & 1u) : 0u;
            unsigned m = __ballot_sync(0xffffffffu, hit != 0u);
            if (hit) {
                int pos = cnt + __popc(m & ((1u << lane) - 1u));
                if (pos < MAXL) lst[pos] = (unsigned short)i;
            }
            cnt += __popc(m);
        }
        cnt = min(cnt, MAXL);
        int cnt_pad = (cnt + 7) & ~7;
        if (cnt + lane < cnt_pad) lst[cnt + lane] = (unsigned short)ZROW;
        if (lane == 0) {
            g_counts[row] = cnt_pad;
            atomicAdd(&lh[cnt_pad >> 3], 1);
        }
    }
    __syncthreads();
    if (threadIdx.x < NBIN && lh[threadIdx.x])
        atomicAdd(&g_binhist[threadIdx.x], lh[threadIdx.x]);
    // last block computes the exclusive prefix into g_bincur
    __threadfence();
    __syncthreads();
    if (threadIdx.x == 0)
        last = (atomicAdd(&g_done, 1) == LIST_BLK - 1);
    __syncthreads();
    if (last && threadIdx.x == 0) {
        int s = 0;
#pragma unroll
        for (int bin = 0; bin < NBIN; bin++) { int v = g_binhist[bin]; g_bincur[bin] = s; s += v; }
    }
}

// ---------------- K2b: place (folded) + sparse hidden GEMM ---------------------
// 148 blocks, 1/SM, all co-resident -> software grid barrier is safe.
// Prologue: each block scatters its 433 rows into g_order (warp-aggregated
// atomics), then grid barrier. Main: 37 groups x 4 super-slices interleave.
__global__ __launch_bounds__(1024, 1) void k_phaseA() {
    extern __shared__ float sW[];                // [(DIN+1)][HS]
    int warpId = threadIdx.x >> 5, lane = threadIdx.x & 31;

    // ---- folded k_place ----
    {
        int r0 = blockIdx.x * RPB;
        int rend = min(r0 + RPB, NROW);
        for (int row = r0 + (int)threadIdx.x; row < rend; row += 1024) {
            int bin = g_counts[row] >> 3;
            unsigned peers = __match_any_sync(__activemask(), bin);
            int leader = __ffs(peers) - 1;
            int rank = __popc(peers & ((1u << lane) - 1u));
            int base = 0;
            if (rank == 0) base = atomicAdd(&g_bincur[bin], __popc(peers));
            base = __shfl_sync(__activemask(), base, leader);
            g_order[base + rank] = row;
        }
        __threadfence();
        __syncthreads();
        if (threadIdx.x == 0) {
            atomicAdd((int*)&g_bar, 1);
            while (g_bar < GRID_A) { }
        }
        __syncthreads();
    }

    int half = lane >> 4, hl = lane & 15;
    const char* sWb = (const char*)sW + hl * 16;
    int ss = blockIdx.x / NGRP;                   // 0..3 super-slice
    int bg = blockIdx.x % NGRP;                   // 0..36 interleave group

#pragma unroll 1
    for (int sli = 0; sli < 4; sli++) {
        int sl = ss * 4 + sli;
        int h0 = sl * HS;

        __syncthreads();                          // protect sW from previous slice
        for (int e = threadIdx.x; e < (DIN + 1) * (HS / 4); e += 1024) {
            int i = e >> 4, c = e & 15;
            ((float4*)sW)[e] = *(const float4*)&g_Wt[i * H_ + h0 + c * 4];
        }
        __syncthreads();

        for (int k = warpId; k < PPG37; k += 32) {
            int q = bg + k * NGRP;                // global pair id
            if (q >= NPAIR) break;
            int myrow = __ldcg(&g_order[q * 2 + half]);  // L2 read (cross-SM writes)
            int mycnt = g_counts[myrow];
            int pcnt  = max(mycnt, __shfl_xor_sync(0xffffffffu, mycnt, 16));
            const unsigned short* lst = &g_lists[(size_t)myrow * MAXL];
            unsigned long long a0 = 0ull, a1 = 0ull;
            for (int base = 0; base < pcnt; base += 8) {
                uint4 cur;
                if (base < mycnt) cur = *(const uint4*)(lst + base);
                else              cur = make_uint4(ZPACK, ZPACK, ZPACK, ZPACK);
                unsigned j; ulonglong2 wv;
#define STEP(JE) \
                j = (JE); \
                wv = *(const ulonglong2*)(sWb + j * 256u); \
                asm("add.rn.f32x2 %0, %0, %1;" : "+l"(a0) : "l"(wv.x)); \
                asm("add.rn.f32x2 %0, %0, %1;" : "+l"(a1) : "l"(wv.y));
                STEP(cur.x & 0xFFFFu) STEP(cur.x >> 16)
                STEP(cur.y & 0xFFFFu) STEP(cur.y >> 16)
                STEP(cur.z & 0xFFFFu) STEP(cur.z >> 16)
                STEP(cur.w & 0xFFFFu) STEP(cur.w >> 16)
#undef STEP
            }
            ulonglong2 o; o.x = a0; o.y = a1;
            *(ulonglong2*)&g_I[(size_t)myrow * H_ + h0 + hl * 4] = o;
        }
    }
}

// ---------------- K3: hidden LIF recurrence + spike-bit pack -------------------
__global__ void k_rec_hid(const float* __restrict__ hs0, const float* __restrict__ hv0) {
    int b  = blockIdx.x >> 2;
    int hq = blockIdx.x & 3;
    int h  = hq * 256 + threadIdx.x;
    int lane = threadIdx.x & 31;
    float hv = hv0[b * H_ + h];
    float hs = hs0[b * H_ + h];
    const float* Ip = &g_I[(size_t)(b * T_) * H_ + h];
    unsigned* hp = &g_hsb[(size_t)(b * T_) * (H_ / 32) + (h >> 5)];

    for (int t = 0; t < T_; t += 5) {            // 250 % 5 == 0
        float v[5];
#pragma unroll
        for (int k = 0; k < 5; k++) v[k] = Ip[(size_t)(t + k) * H_];
#pragma unroll
        for (int k = 0; k < 5; k++) {
            hv = hv * 0.5f * (1.0f - hs) + v[k];
            bool s = hv > 0.5f;
            hs = s ? 1.0f : 0.0f;
            unsigned m = __ballot_sync(0xffffffffu, s);
            if (lane == 0) hp[(size_t)(t + k) * (H_ / 32)] = m;
        }
    }
}

// ---------------- K4: out GEMM (sparse ffs walk) + fused out recurrence --------
__global__ __launch_bounds__(256) void k_outgemm(const float* __restrict__ os0,
                                                 const float* __restrict__ ov0,
                                                 float* __restrict__ out) {
    extern __shared__ float smem_[];             // sWT [H_*20] + sO [256*20]
    float* sWT = smem_;
    float* sO  = smem_ + H_ * DOUT;
    for (int e = threadIdx.x; e < H_ * DOUT / 4; e += blockDim.x)
        ((float4*)sWT)[e] = ((const float4*)g_WoT)[e];
    __syncthreads();

    int b = blockIdx.x, t = threadIdx.x;
    if (t < T_) {
        const unsigned* wp_ = &g_hsb[(size_t)(b * T_ + t) * (H_ / 32)];
        float2 acc[10];
#pragma unroll
        for (int o = 0; o < 10; o++) acc[o] = make_float2(0.0f, 0.0f);
#pragma unroll 4
        for (int w = 0; w < H_ / 32; w++) {
            unsigned word = wp_[w];
            while (word) {
                int bit = __ffs(word) - 1;
                word &= word - 1;
                const float2* base = (const float2*)&sWT[(w * 32 + bit) * DOUT];
#pragma unroll
                for (int o = 0; o < 10; o++) {
                    float2 v = base[o];
                    acc[o].x += v.x; acc[o].y += v.y;
                }
            }
        }
        float2* od = (float2*)&sO[t * DOUT];
#pragma unroll
        for (int o = 0; o < 10; o++) od[o] = acc[o];
    }
    __syncthreads();

    if (t < DOUT) {
        float ov = ov0[b * DOUT + t];
        float os = os0[b * DOUT + t];
        float cnt = 0.0f;
        for (int tt = 0; tt < T_; tt++) {
            float v = sO[tt * DOUT + t];
            ov = ov * 0.5f * (1.0f - os) + v;
            os = (ov > 0.5f) ? 1.0f : 0.0f;
            cnt += os;
        }
        out[b * DOUT + t] = cnt;
    }
}

// ---------------- launch ------------------------------------------------------
extern "C" void kernel_launch(void* const* d_in, const int* in_sizes, int n_in,
                              void* d_out, int out_size) {
    const float* sd  = (const float*)d_in[0];   // spike_data [256,700,250]
    const float* Wh  = (const float*)d_in[1];   // W_hid [1024,700]
    const float* Wo  = (const float*)d_in[2];   // W_out [20,1024]
    const float* hs0 = (const float*)d_in[3];   // hid_spike0 [256,1024]
    const float* hv0 = (const float*)d_in[4];   // hid_volt0
    const float* os0 = (const float*)d_in[5];   // out_spike0 [256,20]
    const float* ov0 = (const float*)d_in[6];   // out_volt0
    float* out = (float*)d_out;                 // [256,20] fp32
    (void)in_sizes; (void)n_in; (void)out_size;

    int outg_smem = (H_ * DOUT + 256 * DOUT) * 4;   // 80 KB + 20 KB
    cudaFuncSetAttribute(k_phaseA, cudaFuncAttributeMaxDynamicSharedMemorySize, (DIN + 1) * HS * 4);
    cudaFuncSetAttribute(k_outgemm, cudaFuncAttributeMaxDynamicSharedMemorySize, outg_smem);

    k_prep   <<<PACK_BLK + WT_BLK + WO_BLK + 1, 256>>>(sd, Wh, Wo);
    k_lists  <<<LIST_BLK, 256>>>();
    k_phaseA <<<GRID_A, 1024, (DIN + 1) * HS * 4>>>();
    k_rec_hid<<<B_ * 4, 256>>>(hs0, hv0);
    k_outgemm<<<B_, 256, outg_smem>>>(os0, ov0, out);
}